// round 6
// baseline (speedup 1.0000x reference)
#include <cuda_runtime.h>
#include <cuda_bf16.h>
#include <cstdint>

// Problem constants
static constexpr int kS    = 256;
static constexpr int kB    = 16;
static constexpr int kV    = 32000;
static constexpr int kEMB  = 32;
static constexpr int kHID  = 16;
static constexpr int kG    = 4 * kHID;     // 64 gates
static constexpr int kRows = kS * kB;      // 4096
static constexpr int kMT   = 128;          // rows per CTA (m tile)
static constexpr int kNT   = 128;          // cols per CTA (n tile)
static constexpr int kNTiles = kV / kNT;   // 250
static constexpr int kMTiles = kRows / kMT; // 32
static constexpr int kAPad = 36;           // padded k-stride (bank-perfect frags)

// Scratch (static __device__ — no allocations allowed)
__device__ float g_gx[kS * kB * kG];
__device__ float g_concat[kRows * 2 * kHID];          // A matrix [4096][32]
__device__ float g_part[kNTiles * kRows];             // per-(ntile,row) exp-sums
__device__ float g_lz[kRows];                         // per-row logZ

__device__ __forceinline__ float sigf(float x) {
    return 1.0f / (1.0f + __expf(-x));
}
__device__ __forceinline__ float tanhfast(float x) {
    return 2.0f / (1.0f + __expf(-2.0f * x)) - 1.0f;
}
__device__ __forceinline__ uint32_t cvt_tf32(float x) {
    uint32_t u;
    asm("cvt.rna.tf32.f32 %0, %1;" : "=r"(u) : "f"(x));
    return u;
}
__device__ __forceinline__ void mma_tf32(float c[4], uint32_t a0, uint32_t a1,
                                         uint32_t a2, uint32_t a3,
                                         uint32_t b0, uint32_t b1) {
    asm("mma.sync.aligned.m16n8k8.row.col.f32.tf32.tf32.f32 "
        "{%0,%1,%2,%3}, {%4,%5,%6,%7}, {%8,%9}, {%0,%1,%2,%3};"
        : "+f"(c[0]), "+f"(c[1]), "+f"(c[2]), "+f"(c[3])
        : "r"(a0), "r"(a1), "r"(a2), "r"(a3), "r"(b0), "r"(b1));
}

// ---------------------------------------------------------------------------
// Kernel 0: Gx = x@W_ih.T + b_ih + b_hh (shared by both scan directions)
// ---------------------------------------------------------------------------
__global__ void gx_kernel(const int* __restrict__ tokens,
                          const float* __restrict__ emb,
                          const float* __restrict__ W_ih,
                          const float* __restrict__ b_ih,
                          const float* __restrict__ b_hh) {
    __shared__ float ws[kG * 33];
    __shared__ float xs[4][32];
    __shared__ float bb[kG];

    int tid = threadIdx.x;
    for (int i = tid; i < kG * kEMB; i += 256)
        ws[(i >> 5) * 33 + (i & 31)] = W_ih[i];
    if (tid < kG) bb[tid] = b_ih[tid] + b_hh[tid];

    int sb0 = blockIdx.x * 4;
    if (tid < 128) {
        int g = tid >> 5, k = tid & 31;
        xs[g][k] = emb[(size_t)tokens[sb0 + g] * kEMB + k];
    }
    __syncthreads();

    int g = tid >> 6;
    int j = tid & (kG - 1);
    const float* wr = ws + j * 33;
    float a0 = bb[j], a1 = 0.f, a2 = 0.f, a3 = 0.f;
#pragma unroll
    for (int k = 0; k < kEMB; k += 4) {
        a0 += xs[g][k + 0] * wr[k + 0];
        a1 += xs[g][k + 1] * wr[k + 1];
        a2 += xs[g][k + 2] * wr[k + 2];
        a3 += xs[g][k + 3] * wr[k + 3];
    }
    g_gx[(sb0 + g) * kG + j] = (a0 + a1) + (a2 + a3);
}

// ---------------------------------------------------------------------------
// Kernel 1: LSTM recurrence. 32 blocks = (2 dirs) x (16 batch lanes).
// ---------------------------------------------------------------------------
__global__ void lstm_kernel(const float* __restrict__ W_hh,
                            const float* __restrict__ init_h,
                            const float* __restrict__ init_c) {
    int dir = blockIdx.x >> 4;
    int b   = blockIdx.x & 15;
    int j   = threadIdx.x;

    __shared__ float h_sh[kHID];
    __shared__ float gact[kG];

    float w[kHID];
#pragma unroll
    for (int k = 0; k < kHID; ++k) w[k] = W_hh[j * kHID + k];

    float c_reg = 0.f, h_reg = 0.f;
    if (j < kHID) {
        h_reg = init_h[j];
        c_reg = init_c[j];
        h_sh[j] = h_reg;
    }
    __syncthreads();

    int p  = dir ? (kS - 1) : 0;
    int dp = dir ? -1 : 1;
    float gx_next = g_gx[(p * kB + b) * kG + j];

    for (int step = 0; step < kS; ++step, p += dp) {
        float gxv = gx_next;
        if (step < kS - 1) gx_next = g_gx[((p + dp) * kB + b) * kG + j];

        if (j < kHID)
            g_concat[(p * kB + b) * (2 * kHID) + dir * kHID + j] = h_reg;

        float a0 = 0.f, a1 = 0.f, a2 = 0.f, a3 = 0.f;
#pragma unroll
        for (int k = 0; k < kHID; k += 4) {
            a0 += w[k + 0] * h_sh[k + 0];
            a1 += w[k + 1] * h_sh[k + 1];
            a2 += w[k + 2] * h_sh[k + 2];
            a3 += w[k + 3] * h_sh[k + 3];
        }
        float pre = gxv + ((a0 + a1) + (a2 + a3));
        gact[j] = (j >= 32 && j < 48) ? tanhfast(pre) : sigf(pre);
        __syncthreads();

        if (j < kHID) {
            float ig = gact[j];
            float fg = gact[kHID + j];
            float gg = gact[2 * kHID + j];
            float og = gact[3 * kHID + j];
            c_reg = fg * c_reg + ig * gg;
            h_reg = og * tanhfast(c_reg);
            h_sh[j] = h_reg;
        }
        __syncthreads();
    }
}

// ---------------------------------------------------------------------------
// Kernel 2: tf32 tensor-core logits GEMM (two template passes).
// CTA = 128 rows x 128 cols, 8 warps (warp w owns rows w*16..w*16+15 x n128).
// Pass 1 (WRITE=false): MMA -> per-row sum(exp) -> g_part[ntile][row].
// Pass 2 (WRITE=true):  MMA with acc init = b_out - logZ -> DIRECT fragment
//   stores: thread (gr,tg) owns cols f*8+tg*2..+1 of rows mrow+gr, mrow+gr+8;
//   STG.64 at 32B-aligned addrs; a warp's 16 f-iters fully tile 8 rows x 128
//   cols, so every 128B line is written whole. No smem transpose needed.
// ---------------------------------------------------------------------------
template <bool WRITE>
__global__ void __launch_bounds__(256, 2)
mma_pass(const float* __restrict__ W_out,
         const float* __restrict__ b_out,
         float* __restrict__ out) {
    __shared__ float A_sm[kMT * kAPad];   // tf32 bit patterns
    __shared__ float B_sm[kNT * kAPad];   // tf32 bit patterns
    __shared__ float bias_sm[kNT];
    __shared__ float lz_sm[kMT];

    int tid  = threadIdx.x;
    int warp = tid >> 5;
    int lane = tid & 31;
    int tg   = lane & 3;     // threadID-in-group
    int gr   = lane >> 2;    // groupID
    int n0   = blockIdx.x * kNT;
    int row0 = blockIdx.y * kMT;
    int mrow = warp * 16;

    // stage A (concat rows) with tf32 rounding; 128x32 floats
    {
        const float4* src = reinterpret_cast<const float4*>(
            g_concat + (size_t)row0 * 32);
        for (int i = tid; i < kMT * 8; i += 256) {
            float4 v = src[i];
            uint4 u = make_uint4(cvt_tf32(v.x), cvt_tf32(v.y),
                                 cvt_tf32(v.z), cvt_tf32(v.w));
            *reinterpret_cast<uint4*>(
                A_sm + (i >> 3) * kAPad + (i & 7) * 4) = u;
        }
    }
    // stage B (W_out rows n0..n0+127)
    {
        const float4* src = reinterpret_cast<const float4*>(
            W_out + (size_t)n0 * 32);
        for (int i = tid; i < kNT * 8; i += 256) {
            float4 v = src[i];
            uint4 u = make_uint4(cvt_tf32(v.x), cvt_tf32(v.y),
                                 cvt_tf32(v.z), cvt_tf32(v.w));
            *reinterpret_cast<uint4*>(
                B_sm + (i >> 3) * kAPad + (i & 7) * 4) = u;
        }
    }
    if (tid < kNT) bias_sm[tid] = b_out[n0 + tid];
    if (WRITE && tid < kMT) lz_sm[tid] = g_lz[row0 + tid];
    __syncthreads();

    // accumulators: 16 n-frags x 4
    float c[16][4];
#pragma unroll
    for (int f = 0; f < 16; ++f) {
        float bx = bias_sm[f * 8 + tg * 2];
        float by = bias_sm[f * 8 + tg * 2 + 1];
        if (WRITE) {
            float z0 = lz_sm[mrow + gr];
            float z1 = lz_sm[mrow + gr + 8];
            c[f][0] = bx - z0; c[f][1] = by - z0;
            c[f][2] = bx - z1; c[f][3] = by - z1;
        } else {
            c[f][0] = bx; c[f][1] = by;
            c[f][2] = bx; c[f][3] = by;
        }
    }

    const uint32_t* Ar0 =
        reinterpret_cast<const uint32_t*>(A_sm) + (mrow + gr) * kAPad;
    const uint32_t* Ar8 = Ar0 + 8 * kAPad;
    const uint32_t* Bp =
        reinterpret_cast<const uint32_t*>(B_sm) + gr * kAPad + tg;

#pragma unroll
    for (int kk = 0; kk < 32; kk += 8) {
        uint32_t a0 = Ar0[kk + tg];
        uint32_t a1 = Ar8[kk + tg];
        uint32_t a2 = Ar0[kk + 4 + tg];
        uint32_t a3 = Ar8[kk + 4 + tg];
#pragma unroll
        for (int f = 0; f < 16; ++f) {
            uint32_t b0 = Bp[f * 8 * kAPad + kk];
            uint32_t b1 = Bp[f * 8 * kAPad + kk + 4];
            mma_tf32(c[f], a0, a1, a2, a3, b0, b1);
        }
    }

    if (!WRITE) {
        // per-row sum(exp); rows mrow+gr and mrow+gr+8
        float s0 = 0.f, s1 = 0.f;
#pragma unroll
        for (int f = 0; f < 16; ++f) {
            s0 += __expf(c[f][0]) + __expf(c[f][1]);
            s1 += __expf(c[f][2]) + __expf(c[f][3]);
        }
        // reduce across the quad (lanes 4g..4g+3 share a row)
        s0 += __shfl_xor_sync(0xffffffffu, s0, 1);
        s0 += __shfl_xor_sync(0xffffffffu, s0, 2);
        s1 += __shfl_xor_sync(0xffffffffu, s1, 1);
        s1 += __shfl_xor_sync(0xffffffffu, s1, 2);
        if (tg == 0) {
            g_part[(size_t)blockIdx.x * kRows + row0 + mrow + gr]     = s0;
            g_part[(size_t)blockIdx.x * kRows + row0 + mrow + gr + 8] = s1;
        }
    } else {
        // direct fragment stores (sector-aligned STG.64, lines fully covered)
        float* orow0 = out + (size_t)(row0 + mrow + gr) * kV + n0 + tg * 2;
        float* orow1 = orow0 + (size_t)8 * kV;
#pragma unroll
        for (int f = 0; f < 16; ++f) {
            *reinterpret_cast<float2*>(orow0 + f * 8) =
                make_float2(c[f][0], c[f][1]);
            *reinterpret_cast<float2*>(orow1 + f * 8) =
                make_float2(c[f][2], c[f][3]);
        }
    }
}

// ---------------------------------------------------------------------------
// Kernel 3: logZ reduce over n-tiles. 128 blocks x 32 threads: warp per
// 32-row slab, coalesced 128B loads, fixed-order deterministic sum.
// ---------------------------------------------------------------------------
__global__ void logz_kernel() {
    int row = blockIdx.x * 32 + threadIdx.x;
    float s0 = 0.f, s1 = 0.f;
#pragma unroll 2
    for (int t = 0; t < kNTiles; t += 2) {
        s0 += g_part[(size_t)t * kRows + row];
        s1 += g_part[(size_t)(t + 1) * kRows + row];
    }
    g_lz[row] = __logf(s0 + s1);
}

// ---------------------------------------------------------------------------
extern "C" void kernel_launch(void* const* d_in, const int* in_sizes, int n_in,
                              void* d_out, int out_size) {
    const int*   tokens = (const int*)d_in[0];
    const float* emb    = (const float*)d_in[1];
    const float* W_ih   = (const float*)d_in[2];
    const float* W_hh   = (const float*)d_in[3];
    const float* b_ih   = (const float*)d_in[4];
    const float* b_hh   = (const float*)d_in[5];
    const float* W_out  = (const float*)d_in[6];
    const float* b_out  = (const float*)d_in[7];
    const float* init_h = (const float*)d_in[8];
    const float* init_c = (const float*)d_in[9];
    float* out = (float*)d_out;

    dim3 grid(kNTiles, kMTiles);

    gx_kernel<<<(kS * kB) / 4, 256>>>(tokens, emb, W_ih, b_ih, b_hh);
    lstm_kernel<<<32, 64>>>(W_hh, init_h, init_c);
    mma_pass<false><<<grid, 256>>>(W_out, b_out, out);
    logz_kernel<<<kRows / 32, 32>>>();
    mma_pass<true><<<grid, 256>>>(W_out, b_out, out);
}

// round 7
// speedup vs baseline: 1.1130x; 1.1130x over previous
#include <cuda_runtime.h>
#include <cuda_bf16.h>
#include <cstdint>

// Problem constants
static constexpr int kS    = 256;
static constexpr int kB    = 16;
static constexpr int kV    = 32000;
static constexpr int kEMB  = 32;
static constexpr int kHID  = 16;
static constexpr int kG    = 4 * kHID;     // 64 gates
static constexpr int kRows = kS * kB;      // 4096
static constexpr int kMT   = 128;          // rows per m tile
static constexpr int kNT   = 128;          // cols per CTA (n tile)
static constexpr int kNTiles = kV / kNT;   // 250
static constexpr int kMTiles = kRows / kMT; // 32
static constexpr int kMLoop = 4;           // m tiles per CTA (B reuse)
static constexpr int kAPad = 36;           // padded k-stride (bank-perfect frags)

// Scratch (static __device__ — no allocations allowed)
__device__ float g_gx[kS * kB * kG];
__device__ float g_concat[kRows * 2 * kHID];          // A matrix [4096][32]
__device__ float g_part[kNTiles * kRows];             // per-(ntile,row) exp-sums
__device__ float g_lz[kRows];                         // per-row logZ

__device__ __forceinline__ float sigf(float x) {
    return 1.0f / (1.0f + __expf(-x));
}
__device__ __forceinline__ float tanhfast(float x) {
    return 2.0f / (1.0f + __expf(-2.0f * x)) - 1.0f;
}
__device__ __forceinline__ uint32_t cvt_tf32(float x) {
    uint32_t u;
    asm("cvt.rna.tf32.f32 %0, %1;" : "=r"(u) : "f"(x));
    return u;
}
__device__ __forceinline__ void mma_tf32(float c[4], uint32_t a0, uint32_t a1,
                                         uint32_t a2, uint32_t a3,
                                         uint32_t b0, uint32_t b1) {
    asm("mma.sync.aligned.m16n8k8.row.col.f32.tf32.tf32.f32 "
        "{%0,%1,%2,%3}, {%4,%5,%6,%7}, {%8,%9}, {%0,%1,%2,%3};"
        : "+f"(c[0]), "+f"(c[1]), "+f"(c[2]), "+f"(c[3])
        : "r"(a0), "r"(a1), "r"(a2), "r"(a3), "r"(b0), "r"(b1));
}

// ---------------------------------------------------------------------------
// Kernel 0: Gx = x@W_ih.T + b_ih + b_hh (shared by both scan directions)
// ---------------------------------------------------------------------------
__global__ void gx_kernel(const int* __restrict__ tokens,
                          const float* __restrict__ emb,
                          const float* __restrict__ W_ih,
                          const float* __restrict__ b_ih,
                          const float* __restrict__ b_hh) {
    __shared__ float ws[kG * 33];
    __shared__ float xs[4][32];
    __shared__ float bb[kG];

    int tid = threadIdx.x;
    for (int i = tid; i < kG * kEMB; i += 256)
        ws[(i >> 5) * 33 + (i & 31)] = W_ih[i];
    if (tid < kG) bb[tid] = b_ih[tid] + b_hh[tid];

    int sb0 = blockIdx.x * 4;
    if (tid < 128) {
        int g = tid >> 5, k = tid & 31;
        xs[g][k] = emb[(size_t)tokens[sb0 + g] * kEMB + k];
    }
    __syncthreads();

    int g = tid >> 6;
    int j = tid & (kG - 1);
    const float* wr = ws + j * 33;
    float a0 = bb[j], a1 = 0.f, a2 = 0.f, a3 = 0.f;
#pragma unroll
    for (int k = 0; k < kEMB; k += 4) {
        a0 += xs[g][k + 0] * wr[k + 0];
        a1 += xs[g][k + 1] * wr[k + 1];
        a2 += xs[g][k + 2] * wr[k + 2];
        a3 += xs[g][k + 3] * wr[k + 3];
    }
    g_gx[(sb0 + g) * kG + j] = (a0 + a1) + (a2 + a3);
}

// ---------------------------------------------------------------------------
// Kernel 1: LSTM recurrence. 32 blocks = (2 dirs) x (16 batch lanes).
// ---------------------------------------------------------------------------
__global__ void lstm_kernel(const float* __restrict__ W_hh,
                            const float* __restrict__ init_h,
                            const float* __restrict__ init_c) {
    int dir = blockIdx.x >> 4;
    int b   = blockIdx.x & 15;
    int j   = threadIdx.x;

    __shared__ float h_sh[kHID];
    __shared__ float gact[kG];

    float w[kHID];
#pragma unroll
    for (int k = 0; k < kHID; ++k) w[k] = W_hh[j * kHID + k];

    float c_reg = 0.f, h_reg = 0.f;
    if (j < kHID) {
        h_reg = init_h[j];
        c_reg = init_c[j];
        h_sh[j] = h_reg;
    }
    __syncthreads();

    int p  = dir ? (kS - 1) : 0;
    int dp = dir ? -1 : 1;
    float gx_next = g_gx[(p * kB + b) * kG + j];

    for (int step = 0; step < kS; ++step, p += dp) {
        float gxv = gx_next;
        if (step < kS - 1) gx_next = g_gx[((p + dp) * kB + b) * kG + j];

        if (j < kHID)
            g_concat[(p * kB + b) * (2 * kHID) + dir * kHID + j] = h_reg;

        float a0 = 0.f, a1 = 0.f, a2 = 0.f, a3 = 0.f;
#pragma unroll
        for (int k = 0; k < kHID; k += 4) {
            a0 += w[k + 0] * h_sh[k + 0];
            a1 += w[k + 1] * h_sh[k + 1];
            a2 += w[k + 2] * h_sh[k + 2];
            a3 += w[k + 3] * h_sh[k + 3];
        }
        float pre = gxv + ((a0 + a1) + (a2 + a3));
        gact[j] = (j >= 32 && j < 48) ? tanhfast(pre) : sigf(pre);
        __syncthreads();

        if (j < kHID) {
            float ig = gact[j];
            float fg = gact[kHID + j];
            float gg = gact[2 * kHID + j];
            float og = gact[3 * kHID + j];
            c_reg = fg * c_reg + ig * gg;
            h_reg = og * tanhfast(c_reg);
            h_sh[j] = h_reg;
        }
        __syncthreads();
    }
}

// ---------------------------------------------------------------------------
// Kernel 2: tf32 tensor-core logits GEMM (two template passes).
// Grid (250, 8): each CTA stages one B tile (128 cols) ONCE, then loops over
// 4 m-tiles (A restaged per iter -> B L2 traffic cut 4x, fewer CTAs).
// Pass 1 (WRITE=false): MMA -> per-row sum(exp) -> g_part[ntile][row].
// Pass 2 (WRITE=true):  MMA with acc init = b_out - logZ -> direct fragment
//   stores (STG.64 at 32B-aligned addrs; each warp fully covers its lines).
// ---------------------------------------------------------------------------
template <bool WRITE>
__global__ void __launch_bounds__(256, 2)
mma_pass(const float* __restrict__ W_out,
         const float* __restrict__ b_out,
         float* __restrict__ out) {
    __shared__ float A_sm[kMT * kAPad];   // tf32 bit patterns
    __shared__ float B_sm[kNT * kAPad];   // tf32 bit patterns
    __shared__ float bias_sm[kNT];
    __shared__ float lz_sm[kMT];

    int tid  = threadIdx.x;
    int warp = tid >> 5;
    int lane = tid & 31;
    int tg   = lane & 3;     // threadID-in-group
    int gr   = lane >> 2;    // groupID
    int n0   = blockIdx.x * kNT;
    int mrow = warp * 16;

    // stage B (W_out rows n0..n0+127) once
    {
        const float4* src = reinterpret_cast<const float4*>(
            W_out + (size_t)n0 * 32);
        for (int i = tid; i < kNT * 8; i += 256) {
            float4 v = src[i];
            uint4 u = make_uint4(cvt_tf32(v.x), cvt_tf32(v.y),
                                 cvt_tf32(v.z), cvt_tf32(v.w));
            *reinterpret_cast<uint4*>(
                B_sm + (i >> 3) * kAPad + (i & 7) * 4) = u;
        }
    }
    if (tid < kNT) bias_sm[tid] = b_out[n0 + tid];

    for (int mi = 0; mi < kMLoop; ++mi) {
        int row0 = (blockIdx.y * kMLoop + mi) * kMT;

        __syncthreads();  // prev-iter A readers done / B visible on mi==0
        {
            const float4* src = reinterpret_cast<const float4*>(
                g_concat + (size_t)row0 * 32);
            for (int i = tid; i < kMT * 8; i += 256) {
                float4 v = src[i];
                uint4 u = make_uint4(cvt_tf32(v.x), cvt_tf32(v.y),
                                     cvt_tf32(v.z), cvt_tf32(v.w));
                *reinterpret_cast<uint4*>(
                    A_sm + (i >> 3) * kAPad + (i & 7) * 4) = u;
            }
        }
        if (WRITE && tid < kMT) lz_sm[tid] = g_lz[row0 + tid];
        __syncthreads();

        // accumulators: 16 n-frags x 4
        float c[16][4];
#pragma unroll
        for (int f = 0; f < 16; ++f) {
            float bx = bias_sm[f * 8 + tg * 2];
            float by = bias_sm[f * 8 + tg * 2 + 1];
            if (WRITE) {
                float z0 = lz_sm[mrow + gr];
                float z1 = lz_sm[mrow + gr + 8];
                c[f][0] = bx - z0; c[f][1] = by - z0;
                c[f][2] = bx - z1; c[f][3] = by - z1;
            } else {
                c[f][0] = bx; c[f][1] = by;
                c[f][2] = bx; c[f][3] = by;
            }
        }

        const uint32_t* Ar0 =
            reinterpret_cast<const uint32_t*>(A_sm) + (mrow + gr) * kAPad;
        const uint32_t* Ar8 = Ar0 + 8 * kAPad;
        const uint32_t* Bp =
            reinterpret_cast<const uint32_t*>(B_sm) + gr * kAPad + tg;

#pragma unroll
        for (int kk = 0; kk < 32; kk += 8) {
            uint32_t a0 = Ar0[kk + tg];
            uint32_t a1 = Ar8[kk + tg];
            uint32_t a2 = Ar0[kk + 4 + tg];
            uint32_t a3 = Ar8[kk + 4 + tg];
#pragma unroll
            for (int f = 0; f < 16; ++f) {
                uint32_t b0 = Bp[f * 8 * kAPad + kk];
                uint32_t b1 = Bp[f * 8 * kAPad + kk + 4];
                mma_tf32(c[f], a0, a1, a2, a3, b0, b1);
            }
        }

        if (!WRITE) {
            // per-row sum(exp); rows mrow+gr and mrow+gr+8
            float s0 = 0.f, s1 = 0.f;
#pragma unroll
            for (int f = 0; f < 16; ++f) {
                s0 += __expf(c[f][0]) + __expf(c[f][1]);
                s1 += __expf(c[f][2]) + __expf(c[f][3]);
            }
            s0 += __shfl_xor_sync(0xffffffffu, s0, 1);
            s0 += __shfl_xor_sync(0xffffffffu, s0, 2);
            s1 += __shfl_xor_sync(0xffffffffu, s1, 1);
            s1 += __shfl_xor_sync(0xffffffffu, s1, 2);
            if (tg == 0) {
                g_part[(size_t)blockIdx.x * kRows + row0 + mrow + gr]     = s0;
                g_part[(size_t)blockIdx.x * kRows + row0 + mrow + gr + 8] = s1;
            }
        } else {
            // direct fragment stores (32B-aligned STG.64, lines fully covered)
            float* orow0 = out + (size_t)(row0 + mrow + gr) * kV + n0 + tg * 2;
            float* orow1 = orow0 + (size_t)8 * kV;
#pragma unroll
            for (int f = 0; f < 16; ++f) {
                *reinterpret_cast<float2*>(orow0 + f * 8) =
                    make_float2(c[f][0], c[f][1]);
                *reinterpret_cast<float2*>(orow1 + f * 8) =
                    make_float2(c[f][2], c[f][3]);
            }
        }
    }
}

// ---------------------------------------------------------------------------
// Kernel 3: logZ reduce. 128 blocks x 256 threads = 32 rows x 8 t-slices.
// Each thread sums ~31 tiles (coalesced across rows, MLP via unroll), then a
// deterministic fixed-order 8-way combine per row.
// ---------------------------------------------------------------------------
__global__ void logz_kernel() {
    __shared__ float red[8][32];
    int rl    = threadIdx.x & 31;
    int slice = threadIdx.x >> 5;
    int row   = blockIdx.x * 32 + rl;

    float s = 0.f;
#pragma unroll 4
    for (int t = slice; t < kNTiles; t += 8)
        s += g_part[(size_t)t * kRows + row];
    red[slice][rl] = s;
    __syncthreads();

    if (slice == 0) {
        float tot = 0.f;
#pragma unroll
        for (int i = 0; i < 8; ++i) tot += red[i][rl];
        g_lz[row] = __logf(tot);
    }
}

// ---------------------------------------------------------------------------
extern "C" void kernel_launch(void* const* d_in, const int* in_sizes, int n_in,
                              void* d_out, int out_size) {
    const int*   tokens = (const int*)d_in[0];
    const float* emb    = (const float*)d_in[1];
    const float* W_ih   = (const float*)d_in[2];
    const float* W_hh   = (const float*)d_in[3];
    const float* b_ih   = (const float*)d_in[4];
    const float* b_hh   = (const float*)d_in[5];
    const float* W_out  = (const float*)d_in[6];
    const float* b_out  = (const float*)d_in[7];
    const float* init_h = (const float*)d_in[8];
    const float* init_c = (const float*)d_in[9];
    float* out = (float*)d_out;

    dim3 grid(kNTiles, kMTiles / kMLoop);

    gx_kernel<<<(kS * kB) / 4, 256>>>(tokens, emb, W_ih, b_ih, b_hh);
    lstm_kernel<<<32, 64>>>(W_hh, init_h, init_c);
    mma_pass<false><<<grid, 256>>>(W_out, b_out, out);
    logz_kernel<<<kRows / 32, 256>>>();
    mma_pass<true><<<grid, 256>>>(W_out, b_out, out);
}

// round 8
// speedup vs baseline: 1.1615x; 1.0436x over previous
#include <cuda_runtime.h>
#include <cuda_bf16.h>
#include <cstdint>

// Problem constants
static constexpr int kS    = 256;
static constexpr int kB    = 16;
static constexpr int kV    = 32000;
static constexpr int kEMB  = 32;
static constexpr int kHID  = 16;
static constexpr int kG    = 4 * kHID;     // 64 gates
static constexpr int kRows = kS * kB;      // 4096
static constexpr int kMT   = 128;          // rows per m tile
static constexpr int kNT   = 128;          // cols per CTA (n tile)
static constexpr int kNTiles = kV / kNT;   // 250
static constexpr int kMTiles = kRows / kMT; // 32
static constexpr int kMLoop = 4;           // m tiles per CTA (B reuse)
static constexpr int kFS   = 20;           // fragment-order row stride (float2)

static constexpr float kLOG2E = 1.4426950408889634f;

// Scratch (static __device__ — no allocations allowed)
__device__ float g_gx[kS * kB * kG];
__device__ float g_concat[kRows * 2 * kHID];          // A matrix [4096][32]
__device__ float g_part[kNTiles * kRows];             // per-(ntile,row) exp-sums
__device__ float g_lz[kRows];                         // per-row logZ

__device__ __forceinline__ float sigf(float x) {
    return 1.0f / (1.0f + __expf(-x));
}
__device__ __forceinline__ float tanhfast(float x) {
    return 2.0f / (1.0f + __expf(-2.0f * x)) - 1.0f;
}
__device__ __forceinline__ uint32_t cvt_tf32(float x) {
    uint32_t u;
    asm("cvt.rna.tf32.f32 %0, %1;" : "=r"(u) : "f"(x));
    return u;
}
__device__ __forceinline__ float ex2f(float x) {
    float y;
    asm("ex2.approx.ftz.f32 %0, %1;" : "=f"(y) : "f"(x));
    return y;
}
__device__ __forceinline__ void mma_tf32(float c[4], uint32_t a0, uint32_t a1,
                                         uint32_t a2, uint32_t a3,
                                         uint32_t b0, uint32_t b1) {
    asm("mma.sync.aligned.m16n8k8.row.col.f32.tf32.tf32.f32 "
        "{%0,%1,%2,%3}, {%4,%5,%6,%7}, {%8,%9}, {%0,%1,%2,%3};"
        : "+f"(c[0]), "+f"(c[1]), "+f"(c[2]), "+f"(c[3])
        : "r"(a0), "r"(a1), "r"(a2), "r"(a3), "r"(b0), "r"(b1));
}

// ---------------------------------------------------------------------------
// Kernel 0: Gx = x@W_ih.T + b_ih + b_hh (shared by both scan directions)
// ---------------------------------------------------------------------------
__global__ void gx_kernel(const int* __restrict__ tokens,
                          const float* __restrict__ emb,
                          const float* __restrict__ W_ih,
                          const float* __restrict__ b_ih,
                          const float* __restrict__ b_hh) {
    __shared__ float ws[kG * 33];
    __shared__ float xs[4][32];
    __shared__ float bb[kG];

    int tid = threadIdx.x;
    for (int i = tid; i < kG * kEMB; i += 256)
        ws[(i >> 5) * 33 + (i & 31)] = W_ih[i];
    if (tid < kG) bb[tid] = b_ih[tid] + b_hh[tid];

    int sb0 = blockIdx.x * 4;
    if (tid < 128) {
        int g = tid >> 5, k = tid & 31;
        xs[g][k] = emb[(size_t)tokens[sb0 + g] * kEMB + k];
    }
    __syncthreads();

    int g = tid >> 6;
    int j = tid & (kG - 1);
    const float* wr = ws + j * 33;
    float a0 = bb[j], a1 = 0.f, a2 = 0.f, a3 = 0.f;
#pragma unroll
    for (int k = 0; k < kEMB; k += 4) {
        a0 += xs[g][k + 0] * wr[k + 0];
        a1 += xs[g][k + 1] * wr[k + 1];
        a2 += xs[g][k + 2] * wr[k + 2];
        a3 += xs[g][k + 3] * wr[k + 3];
    }
    g_gx[(sb0 + g) * kG + j] = (a0 + a1) + (a2 + a3);
}

// ---------------------------------------------------------------------------
// Kernel 1: LSTM recurrence. 32 blocks = (2 dirs) x (16 batch lanes).
// ---------------------------------------------------------------------------
__global__ void lstm_kernel(const float* __restrict__ W_hh,
                            const float* __restrict__ init_h,
                            const float* __restrict__ init_c) {
    int dir = blockIdx.x >> 4;
    int b   = blockIdx.x & 15;
    int j   = threadIdx.x;

    __shared__ float h_sh[kHID];
    __shared__ float gact[kG];

    float w[kHID];
#pragma unroll
    for (int k = 0; k < kHID; ++k) w[k] = W_hh[j * kHID + k];

    float c_reg = 0.f, h_reg = 0.f;
    if (j < kHID) {
        h_reg = init_h[j];
        c_reg = init_c[j];
        h_sh[j] = h_reg;
    }
    __syncthreads();

    int p  = dir ? (kS - 1) : 0;
    int dp = dir ? -1 : 1;
    float gx_next = g_gx[(p * kB + b) * kG + j];

    for (int step = 0; step < kS; ++step, p += dp) {
        float gxv = gx_next;
        if (step < kS - 1) gx_next = g_gx[((p + dp) * kB + b) * kG + j];

        if (j < kHID)
            g_concat[(p * kB + b) * (2 * kHID) + dir * kHID + j] = h_reg;

        float a0 = 0.f, a1 = 0.f, a2 = 0.f, a3 = 0.f;
#pragma unroll
        for (int k = 0; k < kHID; k += 4) {
            a0 += w[k + 0] * h_sh[k + 0];
            a1 += w[k + 1] * h_sh[k + 1];
            a2 += w[k + 2] * h_sh[k + 2];
            a3 += w[k + 3] * h_sh[k + 3];
        }
        float pre = gxv + ((a0 + a1) + (a2 + a3));
        gact[j] = (j >= 32 && j < 48) ? tanhfast(pre) : sigf(pre);
        __syncthreads();

        if (j < kHID) {
            float ig = gact[j];
            float fg = gact[kHID + j];
            float gg = gact[2 * kHID + j];
            float og = gact[3 * kHID + j];
            c_reg = fg * c_reg + ig * gg;
            h_reg = og * tanhfast(c_reg);
            h_sh[j] = h_reg;
        }
        __syncthreads();
    }
}

// ---------------------------------------------------------------------------
// Fragment-order staging: smem holds float2{ X[r][q*8+tg], X[r][q*8+4+tg] }
// at float2 index r*kFS + q*4 + tg. LDS.64 operand fetches are conflict-free
// (bank = 8*gr + 2*tg within each half-warp phase).
// src: row-major [rows][32] floats. scale applied before tf32 rounding.
// ---------------------------------------------------------------------------
__device__ __forceinline__ void stage_frag(float* dst, const float4* src,
                                           int rows, int tid, float scale) {
    for (int i = tid; i < rows * 8; i += 256) {
        float4 v = src[i];
        int r = i >> 3, q = (i & 7) >> 1, half = i & 1;
        float* p = dst + (r * kFS + q * 4) * 2 + half;
        p[0] = __uint_as_float(cvt_tf32(v.x * scale));
        p[2] = __uint_as_float(cvt_tf32(v.y * scale));
        p[4] = __uint_as_float(cvt_tf32(v.z * scale));
        p[6] = __uint_as_float(cvt_tf32(v.w * scale));
    }
}

// ---------------------------------------------------------------------------
// Kernel 2: tf32 tensor-core logits GEMM (two template passes).
// Grid (250, 8): each CTA stages one B tile once, loops over 4 m-tiles.
// Pass 1 (WRITE=false): A,bias pre-scaled by log2(e); MMA -> sum of
//   ex2.approx over the tile -> g_part[ntile][row].
// Pass 2 (WRITE=true):  MMA with acc init = b_out - logZ -> direct fragment
//   streaming stores (__stcs, 32B-aligned STG.64; warps fully cover lines).
// ---------------------------------------------------------------------------
template <bool WRITE>
__global__ void __launch_bounds__(256, 2)
mma_pass(const float* __restrict__ W_out,
         const float* __restrict__ b_out,
         float* __restrict__ out) {
    __shared__ float A_sm[kMT * kFS * 2];   // fragment-order tf32 bits
    __shared__ float B_sm[kNT * kFS * 2];
    __shared__ float bias_sm[kNT];
    __shared__ float lz_sm[kMT];

    int tid  = threadIdx.x;
    int warp = tid >> 5;
    int lane = tid & 31;
    int tg   = lane & 3;     // threadID-in-group
    int gr   = lane >> 2;    // groupID
    int n0   = blockIdx.x * kNT;
    int mrow = warp * 16;

    // stage B (W_out rows n0..n0+127) once
    stage_frag(B_sm, reinterpret_cast<const float4*>(W_out + (size_t)n0 * 32),
               kNT, tid, 1.0f);
    if (tid < kNT) bias_sm[tid] = WRITE ? b_out[n0 + tid]
                                        : b_out[n0 + tid] * kLOG2E;

    for (int mi = 0; mi < kMLoop; ++mi) {
        int row0 = (blockIdx.y * kMLoop + mi) * kMT;

        __syncthreads();  // prev-iter A readers done / B visible on mi==0
        stage_frag(A_sm,
                   reinterpret_cast<const float4*>(g_concat + (size_t)row0 * 32),
                   kMT, tid, WRITE ? 1.0f : kLOG2E);
        if (WRITE && tid < kMT) lz_sm[tid] = g_lz[row0 + tid];
        __syncthreads();

        // accumulators: 16 n-frags x 4
        float c[16][4];
#pragma unroll
        for (int f = 0; f < 16; ++f) {
            float bx = bias_sm[f * 8 + tg * 2];
            float by = bias_sm[f * 8 + tg * 2 + 1];
            if (WRITE) {
                float z0 = lz_sm[mrow + gr];
                float z1 = lz_sm[mrow + gr + 8];
                c[f][0] = bx - z0; c[f][1] = by - z0;
                c[f][2] = bx - z1; c[f][3] = by - z1;
            } else {
                c[f][0] = bx; c[f][1] = by;
                c[f][2] = bx; c[f][3] = by;
            }
        }

        const float2* A2 = reinterpret_cast<const float2*>(A_sm);
        const float2* B2 = reinterpret_cast<const float2*>(B_sm);
        const float2* Ar0 = A2 + (mrow + gr) * kFS + tg;
        const float2* Ar1 = A2 + (mrow + gr + 8) * kFS + tg;
        const float2* Bp  = B2 + gr * kFS + tg;

#pragma unroll
        for (int q = 0; q < 4; ++q) {
            float2 fa0 = Ar0[q * 4];   // a0 = .x, a2 = .y
            float2 fa1 = Ar1[q * 4];   // a1 = .x, a3 = .y
            uint32_t a0 = __float_as_uint(fa0.x);
            uint32_t a1 = __float_as_uint(fa1.x);
            uint32_t a2 = __float_as_uint(fa0.y);
            uint32_t a3 = __float_as_uint(fa1.y);
#pragma unroll
            for (int f = 0; f < 16; ++f) {
                float2 fb = Bp[f * 8 * kFS + q * 4];
                mma_tf32(c[f], a0, a1, a2, a3,
                         __float_as_uint(fb.x), __float_as_uint(fb.y));
            }
        }

        if (!WRITE) {
            // per-row sum(2^logit2) = sum(exp(logit)); rows mrow+gr, +8
            float s0 = 0.f, s1 = 0.f;
#pragma unroll
            for (int f = 0; f < 16; ++f) {
                s0 += ex2f(c[f][0]) + ex2f(c[f][1]);
                s1 += ex2f(c[f][2]) + ex2f(c[f][3]);
            }
            s0 += __shfl_xor_sync(0xffffffffu, s0, 1);
            s0 += __shfl_xor_sync(0xffffffffu, s0, 2);
            s1 += __shfl_xor_sync(0xffffffffu, s1, 1);
            s1 += __shfl_xor_sync(0xffffffffu, s1, 2);
            if (tg == 0) {
                g_part[(size_t)blockIdx.x * kRows + row0 + mrow + gr]     = s0;
                g_part[(size_t)blockIdx.x * kRows + row0 + mrow + gr + 8] = s1;
            }
        } else {
            // direct fragment streaming stores (32B-aligned STG.64)
            float* orow0 = out + (size_t)(row0 + mrow + gr) * kV + n0 + tg * 2;
            float* orow1 = orow0 + (size_t)8 * kV;
#pragma unroll
            for (int f = 0; f < 16; ++f) {
                __stcs(reinterpret_cast<float2*>(orow0 + f * 8),
                       make_float2(c[f][0], c[f][1]));
                __stcs(reinterpret_cast<float2*>(orow1 + f * 8),
                       make_float2(c[f][2], c[f][3]));
            }
        }
    }
}

// ---------------------------------------------------------------------------
// Kernel 3: logZ reduce. 128 blocks x 256 threads = 32 rows x 8 t-slices.
// ---------------------------------------------------------------------------
__global__ void logz_kernel() {
    __shared__ float red[8][32];
    int rl    = threadIdx.x & 31;
    int slice = threadIdx.x >> 5;
    int row   = blockIdx.x * 32 + rl;

    float s = 0.f;
#pragma unroll 4
    for (int t = slice; t < kNTiles; t += 8)
        s += g_part[(size_t)t * kRows + row];
    red[slice][rl] = s;
    __syncthreads();

    if (slice == 0) {
        float tot = 0.f;
#pragma unroll
        for (int i = 0; i < 8; ++i) tot += red[i][rl];
        g_lz[row] = __logf(tot);
    }
}

// ---------------------------------------------------------------------------
extern "C" void kernel_launch(void* const* d_in, const int* in_sizes, int n_in,
                              void* d_out, int out_size) {
    const int*   tokens = (const int*)d_in[0];
    const float* emb    = (const float*)d_in[1];
    const float* W_ih   = (const float*)d_in[2];
    const float* W_hh   = (const float*)d_in[3];
    const float* b_ih   = (const float*)d_in[4];
    const float* b_hh   = (const float*)d_in[5];
    const float* W_out  = (const float*)d_in[6];
    const float* b_out  = (const float*)d_in[7];
    const float* init_h = (const float*)d_in[8];
    const float* init_c = (const float*)d_in[9];
    float* out = (float*)d_out;

    dim3 grid(kNTiles, kMTiles / kMLoop);

    gx_kernel<<<(kS * kB) / 4, 256>>>(tokens, emb, W_ih, b_ih, b_hh);
    lstm_kernel<<<32, 64>>>(W_hh, init_h, init_c);
    mma_pass<false><<<grid, 256>>>(W_out, b_out, out);
    logz_kernel<<<kRows / 32, 256>>>();
    mma_pass<true><<<grid, 256>>>(W_out, b_out, out);
}

// round 9
// speedup vs baseline: 1.3200x; 1.1364x over previous
#include <cuda_runtime.h>
#include <cuda_bf16.h>
#include <cstdint>

// Problem constants
static constexpr int kS    = 256;
static constexpr int kB    = 16;
static constexpr int kV    = 32000;
static constexpr int kEMB  = 32;
static constexpr int kHID  = 16;
static constexpr int kG    = 4 * kHID;     // 64 gates
static constexpr int kRows = kS * kB;      // 4096
static constexpr int kMT   = 128;          // rows per m tile
static constexpr int kNT   = 128;          // cols per CTA (n tile)
static constexpr int kNTiles = kV / kNT;   // 250
static constexpr int kMTiles = kRows / kMT; // 32
static constexpr int kMLoop = 4;           // m tiles per CTA (B reuse)
static constexpr int kFS   = 24;           // u32 row stride (conflict-free)

static constexpr float kLOG2E = 1.4426950408889634f;

// Scratch (static __device__ — no allocations allowed)
__device__ float g_gx[kS * kB * kG];
__device__ float g_concat[kRows * 2 * kHID];          // A matrix [4096][32]
__device__ float g_part[kNTiles * kRows];             // per-(ntile,row) exp-sums
__device__ float g_lz[kRows];                         // per-row logZ

__device__ __forceinline__ float sigf(float x) {
    return 1.0f / (1.0f + __expf(-x));
}
__device__ __forceinline__ float tanhfast(float x) {
    return 2.0f / (1.0f + __expf(-2.0f * x)) - 1.0f;
}
__device__ __forceinline__ float ex2f(float x) {
    float y;
    asm("ex2.approx.ftz.f32 %0, %1;" : "=f"(y) : "f"(x));
    return y;
}
__device__ __forceinline__ uint32_t pack_bf16(float lo, float hi) {
    __nv_bfloat162 h = __floats2bfloat162_rn(lo, hi);
    return *reinterpret_cast<uint32_t*>(&h);
}
// m16n8k16 bf16 MMA, fp32 accumulate
__device__ __forceinline__ void mma_bf16(float c[4], uint32_t a0, uint32_t a1,
                                         uint32_t a2, uint32_t a3,
                                         uint32_t b0, uint32_t b1) {
    asm("mma.sync.aligned.m16n8k16.row.col.f32.bf16.bf16.f32 "
        "{%0,%1,%2,%3}, {%4,%5,%6,%7}, {%8,%9}, {%0,%1,%2,%3};"
        : "+f"(c[0]), "+f"(c[1]), "+f"(c[2]), "+f"(c[3])
        : "r"(a0), "r"(a1), "r"(a2), "r"(a3), "r"(b0), "r"(b1));
}

// ---------------------------------------------------------------------------
// Kernel 0: Gx = x@W_ih.T + b_ih + b_hh (shared by both scan directions)
// ---------------------------------------------------------------------------
__global__ void gx_kernel(const int* __restrict__ tokens,
                          const float* __restrict__ emb,
                          const float* __restrict__ W_ih,
                          const float* __restrict__ b_ih,
                          const float* __restrict__ b_hh) {
    __shared__ float ws[kG * 33];
    __shared__ float xs[4][32];
    __shared__ float bb[kG];

    int tid = threadIdx.x;
    for (int i = tid; i < kG * kEMB; i += 256)
        ws[(i >> 5) * 33 + (i & 31)] = W_ih[i];
    if (tid < kG) bb[tid] = b_ih[tid] + b_hh[tid];

    int sb0 = blockIdx.x * 4;
    if (tid < 128) {
        int g = tid >> 5, k = tid & 31;
        xs[g][k] = emb[(size_t)tokens[sb0 + g] * kEMB + k];
    }
    __syncthreads();

    int g = tid >> 6;
    int j = tid & (kG - 1);
    const float* wr = ws + j * 33;
    float a0 = bb[j], a1 = 0.f, a2 = 0.f, a3 = 0.f;
#pragma unroll
    for (int k = 0; k < kEMB; k += 4) {
        a0 += xs[g][k + 0] * wr[k + 0];
        a1 += xs[g][k + 1] * wr[k + 1];
        a2 += xs[g][k + 2] * wr[k + 2];
        a3 += xs[g][k + 3] * wr[k + 3];
    }
    g_gx[(sb0 + g) * kG + j] = (a0 + a1) + (a2 + a3);
}

// ---------------------------------------------------------------------------
// Kernel 1: LSTM recurrence. 32 blocks = (2 dirs) x (16 batch lanes).
// ---------------------------------------------------------------------------
__global__ void lstm_kernel(const float* __restrict__ W_hh,
                            const float* __restrict__ init_h,
                            const float* __restrict__ init_c) {
    int dir = blockIdx.x >> 4;
    int b   = blockIdx.x & 15;
    int j   = threadIdx.x;

    __shared__ float h_sh[kHID];
    __shared__ float gact[kG];

    float w[kHID];
#pragma unroll
    for (int k = 0; k < kHID; ++k) w[k] = W_hh[j * kHID + k];

    float c_reg = 0.f, h_reg = 0.f;
    if (j < kHID) {
        h_reg = init_h[j];
        c_reg = init_c[j];
        h_sh[j] = h_reg;
    }
    __syncthreads();

    int p  = dir ? (kS - 1) : 0;
    int dp = dir ? -1 : 1;
    float gx_next = g_gx[(p * kB + b) * kG + j];

    for (int step = 0; step < kS; ++step, p += dp) {
        float gxv = gx_next;
        if (step < kS - 1) gx_next = g_gx[((p + dp) * kB + b) * kG + j];

        if (j < kHID)
            g_concat[(p * kB + b) * (2 * kHID) + dir * kHID + j] = h_reg;

        float a0 = 0.f, a1 = 0.f, a2 = 0.f, a3 = 0.f;
#pragma unroll
        for (int k = 0; k < kHID; k += 4) {
            a0 += w[k + 0] * h_sh[k + 0];
            a1 += w[k + 1] * h_sh[k + 1];
            a2 += w[k + 2] * h_sh[k + 2];
            a3 += w[k + 3] * h_sh[k + 3];
        }
        float pre = gxv + ((a0 + a1) + (a2 + a3));
        gact[j] = (j >= 32 && j < 48) ? tanhfast(pre) : sigf(pre);
        __syncthreads();

        if (j < kHID) {
            float ig = gact[j];
            float fg = gact[kHID + j];
            float gg = gact[2 * kHID + j];
            float og = gact[3 * kHID + j];
            c_reg = fg * c_reg + ig * gg;
            h_reg = og * tanhfast(c_reg);
            h_sh[j] = h_reg;
        }
        __syncthreads();
    }
}

// ---------------------------------------------------------------------------
// bf16 fragment-order staging. k-pair p (= k/2, p in 0..15) of row r is a
// bf16x2 u32 stored at column 2*(p&3) + ((p>>2)&1) + (p>>3)*8, row stride
// kFS=24 u32. A thread's m16n8k16 operands are then single LDS.64s at
// [r*24 + tg*2] (k0-15) and [r*24 + 8 + tg*2] (k16-31); bank start
// (24r + 2tg) mod 32 covers all 16 even banks per phase -> conflict-free.
// ---------------------------------------------------------------------------
__device__ __forceinline__ int fragcol(int p) {
    return 2 * (p & 3) + ((p >> 2) & 1) + (p >> 3) * 8;
}
__device__ __forceinline__ void stage_bf16(uint32_t* dst, const float4* src,
                                           int rows, int tid, float scale) {
    for (int i = tid; i < rows * 8; i += 256) {
        float4 v = src[i];
        int r = i >> 3, j = i & 7;           // float4 j covers k = 4j..4j+3
        dst[r * kFS + fragcol(2 * j)]     = pack_bf16(v.x * scale, v.y * scale);
        dst[r * kFS + fragcol(2 * j + 1)] = pack_bf16(v.z * scale, v.w * scale);
    }
}

// ---------------------------------------------------------------------------
// Kernel 2: bf16 tensor-core logits GEMM (two template passes).
// Grid (250, 8): each CTA stages one B tile once, loops over 4 m-tiles.
// Pass 1 (WRITE=false): A,bias pre-scaled by log2(e); MMA -> sum of
//   ex2.approx over the tile -> g_part[ntile][row].
// Pass 2 (WRITE=true):  MMA with acc init = b_out - logZ -> direct fragment
//   streaming stores (__stcs, 32B-aligned STG.64; warps fully cover lines).
// ---------------------------------------------------------------------------
template <bool WRITE>
__global__ void __launch_bounds__(256, 2)
mma_pass(const float* __restrict__ W_out,
         const float* __restrict__ b_out,
         float* __restrict__ out) {
    __shared__ uint32_t A_sm[kMT * kFS];   // bf16x2 fragment order
    __shared__ uint32_t B_sm[kNT * kFS];
    __shared__ float bias_sm[kNT];
    __shared__ float lz_sm[kMT];

    int tid  = threadIdx.x;
    int warp = tid >> 5;
    int lane = tid & 31;
    int tg   = lane & 3;     // threadID-in-group
    int gr   = lane >> 2;    // groupID
    int n0   = blockIdx.x * kNT;
    int mrow = warp * 16;

    // stage B (W_out rows n0..n0+127) once
    stage_bf16(B_sm, reinterpret_cast<const float4*>(W_out + (size_t)n0 * 32),
               kNT, tid, 1.0f);
    if (tid < kNT) bias_sm[tid] = WRITE ? b_out[n0 + tid]
                                        : b_out[n0 + tid] * kLOG2E;

    for (int mi = 0; mi < kMLoop; ++mi) {
        int row0 = (blockIdx.y * kMLoop + mi) * kMT;

        __syncthreads();  // prev-iter A readers done / B visible on mi==0
        stage_bf16(A_sm,
                   reinterpret_cast<const float4*>(g_concat + (size_t)row0 * 32),
                   kMT, tid, WRITE ? 1.0f : kLOG2E);
        if (WRITE && tid < kMT) lz_sm[tid] = g_lz[row0 + tid];
        __syncthreads();

        // accumulators: 16 n-frags x 4
        float c[16][4];
#pragma unroll
        for (int f = 0; f < 16; ++f) {
            float bx = bias_sm[f * 8 + tg * 2];
            float by = bias_sm[f * 8 + tg * 2 + 1];
            if (WRITE) {
                float z0 = lz_sm[mrow + gr];
                float z1 = lz_sm[mrow + gr + 8];
                c[f][0] = bx - z0; c[f][1] = by - z0;
                c[f][2] = bx - z1; c[f][3] = by - z1;
            } else {
                c[f][0] = bx; c[f][1] = by;
                c[f][2] = bx; c[f][3] = by;
            }
        }

        // A fragments for this warp's two row groups
        const uint32_t* ar0 = A_sm + (mrow + gr) * kFS + tg * 2;
        const uint32_t* ar1 = A_sm + (mrow + gr + 8) * kFS + tg * 2;
        uint2 alo0 = *reinterpret_cast<const uint2*>(ar0);      // a0,a2 k0-15
        uint2 alo1 = *reinterpret_cast<const uint2*>(ar1);      // a1,a3 k0-15
        uint2 ahi0 = *reinterpret_cast<const uint2*>(ar0 + 8);  // k16-31
        uint2 ahi1 = *reinterpret_cast<const uint2*>(ar1 + 8);
        const uint32_t* bp = B_sm + gr * kFS + tg * 2;

#pragma unroll
        for (int f = 0; f < 16; ++f) {
            uint2 blo = *reinterpret_cast<const uint2*>(bp + f * 8 * kFS);
            uint2 bhi = *reinterpret_cast<const uint2*>(bp + f * 8 * kFS + 8);
            mma_bf16(c[f], alo0.x, alo1.x, alo0.y, alo1.y, blo.x, blo.y);
            mma_bf16(c[f], ahi0.x, ahi1.x, ahi0.y, ahi1.y, bhi.x, bhi.y);
        }

        if (!WRITE) {
            // per-row sum(2^logit2) = sum(exp(logit)); rows mrow+gr, +8
            float s0 = 0.f, s1 = 0.f;
#pragma unroll
            for (int f = 0; f < 16; ++f) {
                s0 += ex2f(c[f][0]) + ex2f(c[f][1]);
                s1 += ex2f(c[f][2]) + ex2f(c[f][3]);
            }
            s0 += __shfl_xor_sync(0xffffffffu, s0, 1);
            s0 += __shfl_xor_sync(0xffffffffu, s0, 2);
            s1 += __shfl_xor_sync(0xffffffffu, s1, 1);
            s1 += __shfl_xor_sync(0xffffffffu, s1, 2);
            if (tg == 0) {
                g_part[(size_t)blockIdx.x * kRows + row0 + mrow + gr]     = s0;
                g_part[(size_t)blockIdx.x * kRows + row0 + mrow + gr + 8] = s1;
            }
        } else {
            // direct fragment streaming stores (32B-aligned STG.64)
            float* orow0 = out + (size_t)(row0 + mrow + gr) * kV + n0 + tg * 2;
            float* orow1 = orow0 + (size_t)8 * kV;
#pragma unroll
            for (int f = 0; f < 16; ++f) {
                __stcs(reinterpret_cast<float2*>(orow0 + f * 8),
                       make_float2(c[f][0], c[f][1]));
                __stcs(reinterpret_cast<float2*>(orow1 + f * 8),
                       make_float2(c[f][2], c[f][3]));
            }
        }
    }
}

// ---------------------------------------------------------------------------
// Kernel 3: logZ reduce. 128 blocks x 256 threads = 32 rows x 8 t-slices.
// ---------------------------------------------------------------------------
__global__ void logz_kernel() {
    __shared__ float red[8][32];
    int rl    = threadIdx.x & 31;
    int slice = threadIdx.x >> 5;
    int row   = blockIdx.x * 32 + rl;

    float s = 0.f;
#pragma unroll 4
    for (int t = slice; t < kNTiles; t += 8)
        s += g_part[(size_t)t * kRows + row];
    red[slice][rl] = s;
    __syncthreads();

    if (slice == 0) {
        float tot = 0.f;
#pragma unroll
        for (int i = 0; i < 8; ++i) tot += red[i][rl];
        g_lz[row] = __logf(tot);
    }
}

// ---------------------------------------------------------------------------
extern "C" void kernel_launch(void* const* d_in, const int* in_sizes, int n_in,
                              void* d_out, int out_size) {
    const int*   tokens = (const int*)d_in[0];
    const float* emb    = (const float*)d_in[1];
    const float* W_ih   = (const float*)d_in[2];
    const float* W_hh   = (const float*)d_in[3];
    const float* b_ih   = (const float*)d_in[4];
    const float* b_hh   = (const float*)d_in[5];
    const float* W_out  = (const float*)d_in[6];
    const float* b_out  = (const float*)d_in[7];
    const float* init_h = (const float*)d_in[8];
    const float* init_c = (const float*)d_in[9];
    float* out = (float*)d_out;

    dim3 grid(kNTiles, kMTiles / kMLoop);

    gx_kernel<<<(kS * kB) / 4, 256>>>(tokens, emb, W_ih, b_ih, b_hh);
    lstm_kernel<<<32, 64>>>(W_hh, init_h, init_c);
    mma_pass<false><<<grid, 256>>>(W_out, b_out, out);
    logz_kernel<<<kRows / 32, 256>>>();
    mma_pass<true><<<grid, 256>>>(W_out, b_out, out);
}